// round 15
// baseline (speedup 1.0000x reference)
#include <cuda_runtime.h>
#include <cuda_fp16.h>
#include <cstdint>
#include <cstddef>

#define T_STEPS 512
#define BATCH   32
#define HID     1024
#define GDIM    4096
#define MROWS   16384          // T*B
#define YW      2048           // 2*H

typedef unsigned long long ull;

// ---------------- device scratch (no runtime allocation) ----------------
__device__ float g_gx[134217728];          // [2][MROWS][GDIM]  512 MB
__device__ __half g_hH[2][2][32 * 1024];   // [dir][parity][b*1024+k] fp16
__device__ unsigned g_bar_cnt[2]   = {0, 0};
__device__ unsigned g_bar_phase[2] = {0, 0};
__device__ __half g_wih[36700160];         // w_ih fp16 (all 6)
__device__ __half g_act[33554432];         // activations fp16 [16384 x 2048]
// W_hh baked per-thread fragment streams (16 warps = 4 mi x 4 kq):
// [ld 6][cb 64][wr 16][kt 16][lane 32] x 16B (one fp16 A-fragment)
__device__ uint4 g_wrec[3145728];          // 48 MB

// ---------------- helpers ----------------
__device__ __forceinline__ uint32_t smem_u32(const void* p) {
    uint32_t a;
    asm("{ .reg .u64 t; cvta.to.shared.u64 t, %1; cvt.u32.u64 %0, t; }" : "=r"(a) : "l"(p));
    return a;
}
#define SW128(o) ((o) ^ (((o) >> 3) & 0x70))

#define MMA_F16(d, a, b0v, b1v)                                               \
    asm volatile("mma.sync.aligned.m16n8k16.row.col.f32.f16.f16.f32 "         \
        "{%0,%1,%2,%3}, {%4,%5,%6,%7}, {%8,%9}, {%0,%1,%2,%3};"               \
        : "+f"((d)[0]), "+f"((d)[1]), "+f"((d)[2]), "+f"((d)[3])              \
        : "r"((a)[0]), "r"((a)[1]), "r"((a)[2]), "r"((a)[3]),                 \
          "r"(b0v), "r"(b1v))

#define LDSM4(r, addr)                                                        \
    asm volatile("ldmatrix.sync.aligned.m8n8.x4.shared.b16 "                  \
        "{%0,%1,%2,%3}, [%4];"                                                \
        : "=r"((r)[0]), "=r"((r)[1]), "=r"((r)[2]), "=r"((r)[3])              \
        : "r"(addr))

#define CP_ASYNC16(smaddr, gaddr)                                             \
    asm volatile("cp.async.cg.shared.global [%0], [%1], 16;"                  \
        :: "r"(smaddr), "l"(gaddr) : "memory")
#define CP_COMMIT() asm volatile("cp.async.commit_group;" ::: "memory")
#define CP_WAIT0()  asm volatile("cp.async.wait_group 0;" ::: "memory")
#define CP_WAIT1()  asm volatile("cp.async.wait_group 1;" ::: "memory")

__device__ __forceinline__ float hsig(float v)  { return fminf(fmaxf(fmaf(v, 0.2f, 0.5f), 0.0f), 1.0f); }
__device__ __forceinline__ float clip1(float v) { return fminf(fmaxf(v, -1.0f), 1.0f); }

// sense-reversing grid barrier (proven R9 form)
__device__ __forceinline__ void grid_barrier(int dir, unsigned& sense) {
    __syncthreads();
    sense ^= 1u;
    if (threadIdx.x == 0) {
        unsigned prev;
        asm volatile("atom.add.acq_rel.gpu.u32 %0, [%1], 1;"
                     : "=r"(prev) : "l"(&g_bar_cnt[dir]) : "memory");
        if (prev == 63u) {
            asm volatile("st.relaxed.gpu.u32 [%0], %1;"
                         :: "l"(&g_bar_cnt[dir]), "r"(0u) : "memory");
            unsigned dummy;
            asm volatile("atom.exch.release.gpu.b32 %0, [%1], %2;"
                         : "=r"(dummy) : "l"(&g_bar_phase[dir]), "r"(sense) : "memory");
        } else {
            unsigned ph;
            do {
                __nanosleep(64);
                asm volatile("ld.acquire.gpu.u32 %0, [%1];"
                             : "=r"(ph) : "l"(&g_bar_phase[dir]) : "memory");
            } while (ph != sense);
        }
    }
    __syncthreads();
}

// ---------------- W_hh prep: bake fp16 fragment streams (16-warp layout) ----------------
// Rec warp layout: wr(0..15) -> mi = wr>>2 (gate tile), kq = wr&3 (K quarter).
struct W6 { const float* w[6]; };

__global__ void __launch_bounds__(256)
wrec_prep(W6 p, uint4* __restrict__ out)
{
    const int cb = blockIdx.x;
    const int ld = blockIdx.y;
    const float* __restrict__ w = p.w[ld];
    for (int it = 0; it < 32; it++) {
        int v    = it * 256 + threadIdx.x;   // 0..8191 = 16 wr x 16 kt x 32 lanes
        int wr   = v >> 9;
        int kt   = (v >> 5) & 15;
        int lane = v & 31;
        int mi = wr >> 2, kq = wr & 3;
        unsigned short fr[8];
#pragma unroll
        for (int j = 0; j < 4; j++) {
            int r  = (lane >> 2) + (j & 1) * 8;
            int kc = (lane & 3) * 2 + (j >> 1) * 8;
            int row = mi * HID + cb * 16 + r;
            int k   = kq * 256 + kt * 16 + kc;
#pragma unroll
            for (int e = 0; e < 2; e++) {
                __half h = __float2half_rn(w[(size_t)row * HID + k + e]);
                fr[j * 2 + e] = *(unsigned short*)&h;
            }
        }
        out[(((size_t)(ld * 64 + cb) * 16 + wr) * 16 + kt) * 32 + lane] = *(uint4*)fr;
    }
}

// ---------------- w_ih fp16 conversion (all 6 in one launch) ----------------
__global__ void __launch_bounds__(256)
wih_split(W6 p, __half* __restrict__ out_base)
{
    const int ld = blockIdx.y;
    const size_t woff = (ld == 0) ? 0u :
                        (ld == 1) ? 1310720u :
                        (size_t)2621440u + (size_t)(ld - 2) * 8388608u;
    const int n4 = (ld < 2) ? 327680 : 2097152;
    int i = blockIdx.x * 256 + threadIdx.x;
    if (i >= n4) return;
    float4 v = ((const float4*)p.w[ld])[i];
    __half2* O = (__half2*)(out_base + woff) + i * 2;
    O[0] = __half2(__float2half_rn(v.x), __float2half_rn(v.y));
    O[1] = __half2(__float2half_rn(v.z), __float2half_rn(v.w));
}

// ---------------- tensor-core input-projection GEMM (fp16, 2-stage cp.async) ----------------
#define SMO_A 0
#define SMO_B 16384
#define STAGE_BYTES 32768
#define SMO_BIAS 65536
#define GEMM_SMEM (65536 + 512)

__global__ void __launch_bounds__(256)
gemm_mma(int K, const float* __restrict__ Afp,
         const __half* __restrict__ Ah,
         const __half* __restrict__ WF, const __half* __restrict__ WR,
         const float* __restrict__ bf1, const float* __restrict__ bf2,
         const float* __restrict__ br1, const float* __restrict__ br2,
         float* __restrict__ G)
{
    extern __shared__ char sm[];
    const uint32_t smb = smem_u32(sm);
    const int tid  = threadIdx.x;
    const int wid  = tid >> 5;
    const int lane = tid & 31;
    const int z    = blockIdx.z;

    const __half* __restrict__ W  = z ? WR  : WF;
    const float* __restrict__ b1 = z ? br1 : bf1;
    const float* __restrict__ b2 = z ? br2 : bf2;
    float* __restrict__ Gz = G + (size_t)z * MROWS * GDIM;

    const int n0 = blockIdx.x * 128;
    const int m0 = blockIdx.y * 128;
    const int wm = (wid >> 2) * 64;
    const int wn = (wid & 3) * 32;

    {
        float* bias = (float*)(sm + SMO_BIAS);
        if (tid < 128) bias[tid] = b1[n0 + tid] + b2[n0 + tid];
    }

    float acc[4][4][4];
#pragma unroll
    for (int mi = 0; mi < 4; mi++)
#pragma unroll
        for (int ni = 0; ni < 4; ni++)
#pragma unroll
            for (int e = 0; e < 4; e++) acc[mi][ni][e] = 0.0f;

    const int nk = K >> 6;

    int srow[4], scol[4];
    uint32_t soff[4];
#pragma unroll
    for (int i = 0; i < 4; i++) {
        int v = tid + i * 256;
        srow[i] = v >> 3;
        scol[i] = (v & 7) * 8;
        soff[i] = SW128((uint32_t)(srow[i] * 128 + (v & 7) * 16));
    }

#define GEMM_MMA_CHUNK(SB)                                                    \
    {                                                                         \
        _Pragma("unroll")                                                     \
        for (int ks = 0; ks < 4; ks++) {                                      \
            uint32_t ah[4][4], bh[2][4];                                      \
            _Pragma("unroll")                                                 \
            for (int mi = 0; mi < 4; mi++) {                                  \
                uint32_t off = SW128((uint32_t)(                              \
                    (wm + mi * 16 + (lane & 15)) * 128 + ks * 32 + (lane >> 4) * 16)); \
                LDSM4(ah[mi], smb + (SB) + SMO_A + off);                      \
            }                                                                 \
            _Pragma("unroll")                                                 \
            for (int p = 0; p < 2; p++) {                                     \
                int q  = lane >> 3;                                           \
                int nf = q >> 1, kl = q & 1;                                  \
                uint32_t off = SW128((uint32_t)(                              \
                    (wn + p * 16 + nf * 8 + (lane & 7)) * 128 + ks * 32 + kl * 16)); \
                LDSM4(bh[p], smb + (SB) + SMO_B + off);                       \
            }                                                                 \
            _Pragma("unroll")                                                 \
            for (int mi = 0; mi < 4; mi++) {                                  \
                _Pragma("unroll")                                             \
                for (int ni = 0; ni < 4; ni++) {                              \
                    const int p = ni >> 1, s = (ni & 1) * 2;                  \
                    MMA_F16(acc[mi][ni], ah[mi], bh[p][s], bh[p][s + 1]);     \
                }                                                             \
            }                                                                 \
        }                                                                     \
    }

    if (Afp) {
        for (int ch = 0; ch < nk; ch++) {
            const int kc = ch * 64;
            __syncthreads();
#pragma unroll
            for (int i = 0; i < 4; i++) {
                size_t ga = (size_t)(m0 + srow[i]) * K + kc + scol[i];
                size_t gb = (size_t)(n0 + srow[i]) * K + kc + scol[i];
                float4 f0 = *(const float4*)(Afp + ga);
                float4 f1 = *(const float4*)(Afp + ga + 4);
                float fv[8] = {f0.x, f0.y, f0.z, f0.w, f1.x, f1.y, f1.z, f1.w};
                unsigned short hh[8];
#pragma unroll
                for (int j = 0; j < 8; j++) {
                    __half h = __float2half_rn(fv[j]);
                    hh[j] = *(unsigned short*)&h;
                }
                *(uint4*)(sm + SMO_A + soff[i]) = *(uint4*)hh;
                *(uint4*)(sm + SMO_B + soff[i]) = *(const uint4*)(W + gb);
            }
            __syncthreads();
            GEMM_MMA_CHUNK(0u)
        }
    } else {
#define GEMM_STAGE(CH, PB)                                                    \
        {                                                                     \
            const int kc_ = (CH) * 64;                                        \
            const uint32_t sb_ = (uint32_t)(PB) * STAGE_BYTES;                \
            _Pragma("unroll")                                                 \
            for (int i = 0; i < 4; i++) {                                     \
                size_t ga = (size_t)(m0 + srow[i]) * K + kc_ + scol[i];       \
                size_t gb = (size_t)(n0 + srow[i]) * K + kc_ + scol[i];       \
                CP_ASYNC16(smb + sb_ + SMO_A + soff[i], Ah + ga);             \
                CP_ASYNC16(smb + sb_ + SMO_B + soff[i], W + gb);              \
            }                                                                 \
        }
        GEMM_STAGE(0, 0)
        CP_COMMIT();
        for (int ch = 0; ch < nk; ch++) {
            if (ch + 1 < nk) {
                GEMM_STAGE(ch + 1, (ch + 1) & 1)
                CP_COMMIT();
                CP_WAIT1();
            } else {
                CP_WAIT0();
            }
            __syncthreads();
            const uint32_t sb = (uint32_t)(ch & 1) * STAGE_BYTES;
            GEMM_MMA_CHUNK(sb)
            __syncthreads();
        }
#undef GEMM_STAGE
    }

    const float* bias = (const float*)(sm + SMO_BIAS);
    const int qr = lane >> 2;
    const int qc = (lane & 3) * 2;
#pragma unroll
    for (int mi = 0; mi < 4; mi++) {
#pragma unroll
        for (int ni = 0; ni < 4; ni++) {
            int col = wn + ni * 8 + qc;
            float bx = bias[col], by = bias[col + 1];
            size_t base0 = (size_t)(m0 + wm + mi * 16 + qr) * GDIM + n0 + col;
            size_t base1 = base0 + (size_t)8 * GDIM;
            *(float2*)&Gz[base0] = make_float2(acc[mi][ni][0] + bx, acc[mi][ni][1] + by);
            *(float2*)&Gz[base1] = make_float2(acc[mi][ni][2] + bx, acc[mi][ni][3] + by);
        }
    }
}

// ---------------- persistent fp16 tensor-core recurrence (16 warps) ----------------
// 128 CTAs x 512 threads. dir = blockIdx.x>>6; CTA owns 16 units (64 gate rows).
// Warp wr: mi = wr>>2 (gate tile), kq = wr&3 (K quarter). Warp = m16 x n32 x K256.
// fp16 single plane; W depth-4 register ring; gx double-buffered, staged pre-barrier.
#define RSM_H  0
#define RSM_G  65536
#define RSM_GX (65536 + 4*64*33*4)              // 99328
#define GXBUF_SZ (32*68*4)                      // 8704 per buffer
#define REC_SMEM (99328 + 2*GXBUF_SZ)           // 116736 B

__global__ void __launch_bounds__(512)
rec_kernel(const uint4* __restrict__ wrec,
           const float* __restrict__ h0, const float* __restrict__ c0,
           int layer, const float* __restrict__ gx,
           float* __restrict__ yfp, __half* __restrict__ yh)
{
    extern __shared__ char sm[];
    const uint32_t smb = smem_u32(sm);
    float* Gp = (float*)(sm + RSM_G);          // 4 x [64][33] K-quarter partials

    const int tid  = threadIdx.x;
    const int lane = tid & 31;
    const int wr   = tid >> 5;                 // warp 0..15
    const int mi   = wr >> 2;                  // gate tile
    const int kq   = wr & 3;                   // K quarter
    const int dir  = blockIdx.x >> 6;
    const int cb   = blockIdx.x & 63;
    const int ld   = layer * 2 + dir;
    const float* __restrict__ gxd = gx + (size_t)dir * MROWS * GDIM;
    // stream per (ld,cb,wr): 16 kt x 32 lanes = 512 uint4; per-kt advance 32
    const uint4* __restrict__ wfrag =
        wrec + ((size_t)(ld * 64 + cb) * 16 + wr) * 512 + lane;

    // c-state: 1 (unit,batch) pair per thread
    const int u_ = tid >> 5;    // maps 512 threads -> 16 units x 32 batch? no: use below
    const int uB = tid >> 5;    // 0..15 (same as wr) -- unit index
    const int bB = tid & 31;    // batch
    (void)u_;
    float cst;
    {
        size_t sidx = (size_t)(2 * layer + dir) * BATCH * HID +
                      (size_t)bB * HID + cb * 16 + uB;
        cst = c0[sidx];
        g_hH[dir][0][bB * 1024 + cb * 16 + uB] = __float2half_rn(h0[sidx]);
    }

    // preload W ring (kt=0..3)
    uint4 pw[4];
#pragma unroll
    for (int s = 0; s < 4; s++) pw[s] = wfrag[s * 32];

    // stage gx for t=0 into buffer 0 (pre-barrier; gx independent of h)
    {
        float* gxb = (float*)(sm + RSM_GX);
        const int te0 = dir ? (T_STEPS - 1) : 0;
        int b = tid >> 4, g = (tid & 15) >> 2, u4 = (tid & 3) * 4;
        float4 d = *(const float4*)(gxd + (size_t)te0 * BATCH * GDIM +
                                    (size_t)b * GDIM + g * HID + cb * 16 + u4);
        *(float4*)(gxb + b * 68 + g * 16 + u4) = d;
    }

    unsigned sense = 0;
    grid_barrier(dir, sense);   // publish initial h

    // ldsm B address components (batches 0-15 and 16-31)
    const int qq = lane >> 3, nf = qq >> 1, kl = qq & 1;
    const uint32_t brow0 = (uint32_t)((nf * 8 + (lane & 7)) * 128 + kl * 16);
    const uint32_t brow1 = brow0 + 16 * 128;

    for (int t = 0; t < T_STEPS; t++) {
        const int par = t & 1;
        const int te  = dir ? (T_STEPS - 1 - t) : t;
        float* gxcur = (float*)(sm + RSM_GX + (t & 1) * GXBUF_SZ);

        // stage h (64KB fp16) into SW128 k64-blocks
        {
            const uint4* hsrc = (const uint4*)&g_hH[dir][par][0];
#pragma unroll
            for (int i = 0; i < 8; i++) {
                int v = tid + i * 512;
                int b = v >> 7;
                int kx = v & 127;
                int blk = kx >> 3, cq = kx & 7;
                uint4 d = __ldcg(hsrc + v);
                *(uint4*)(sm + blk * 4096 + SW128((uint32_t)(b * 128 + cq * 16))) = d;
            }
        }
        __syncthreads();   // h staged; guards G/gx buffer reuse

        float acc[4][4];
#pragma unroll
        for (int s = 0; s < 4; s++)
#pragma unroll
            for (int e = 0; e < 4; e++) acc[s][e] = 0.0f;

#pragma unroll
        for (int kt = 0; kt < 16; kt++) {
            const int rs = kt & 3;
            uint32_t a[4] = {pw[rs].x, pw[rs].y, pw[rs].z, pw[rs].w};
            if (kt + 4 < 16) pw[rs] = wfrag[(kt + 4) * 32];
            const uint32_t blkoff = (uint32_t)((kq * 4 + (kt >> 2)) * 4096);
            const uint32_t cs = (uint32_t)((kt & 3) * 32);
            uint32_t b0[4], b1[4];
            LDSM4(b0, smb + RSM_H + blkoff + SW128(brow0 + cs));
            LDSM4(b1, smb + RSM_H + blkoff + SW128(brow1 + cs));
            MMA_F16(acc[0], a, b0[0], b0[1]);
            MMA_F16(acc[1], a, b0[2], b0[3]);
            MMA_F16(acc[2], a, b1[0], b1[1]);
            MMA_F16(acc[3], a, b1[2], b1[3]);
        }

        // write K-quarter partial G fragments
        {
            float* Gk = Gp + kq * (64 * 33);
            int r0 = mi * 16 + (lane >> 2);
            int cc = (lane & 3) * 2;
#pragma unroll
            for (int s = 0; s < 4; s++) {
                int col = (s >> 1) * 16 + (s & 1) * 8 + cc;
                Gk[r0 * 33 + col]           = acc[s][0];
                Gk[r0 * 33 + col + 1]       = acc[s][1];
                Gk[(r0 + 8) * 33 + col]     = acc[s][2];
                Gk[(r0 + 8) * 33 + col + 1] = acc[s][3];
            }
        }
        __syncthreads();

        // gate combine (sum 4 K-quarter partials) + state update + outputs
        {
            int u = uB, b = bB;
            float gsum[4];
#pragma unroll
            for (int g = 0; g < 4; g++) {
                int off = (g * 16 + u) * 33 + b;
                gsum[g] = (Gp[off] + Gp[off + 2112]) +
                          (Gp[off + 2 * 2112] + Gp[off + 3 * 2112]) +
                          gxcur[b * 68 + g * 16 + u];
            }
            float iv = hsig (gsum[0]);
            float fv = hsig (gsum[1]);
            float gv = clip1(gsum[2]);
            float ov = hsig (gsum[3]);
            float c  = fv * cst + iv * gv;
            cst      = c;
            float h  = ov * clip1(c);
            int gk = cb * 16 + u;
            g_hH[dir][par ^ 1][b * 1024 + gk] = __float2half_rn(h);
            if (yfp) yfp[(size_t)te * BATCH * YW + (size_t)b * YW + dir * HID + gk] = h;
            if (yh)  yh[(size_t)(te * BATCH + b) * YW + dir * HID + gk] = __float2half_rn(h);
        }

        if (t < T_STEPS - 1) {
            // pre-barrier: prefetch next W ring + stage next gx into the other buffer
#pragma unroll
            for (int s = 0; s < 4; s++) pw[s] = wfrag[s * 32];
            {
                float* gxnxt = (float*)(sm + RSM_GX + ((t + 1) & 1) * GXBUF_SZ);
                const int ten = dir ? (T_STEPS - 2 - t) : (t + 1);
                int b = tid >> 4, g = (tid & 15) >> 2, u4 = (tid & 3) * 4;
                float4 d = *(const float4*)(gxd + (size_t)ten * BATCH * GDIM +
                                            (size_t)b * GDIM + g * HID + cb * 16 + u4);
                *(float4*)(gxnxt + b * 68 + g * 16 + u4) = d;
            }
            grid_barrier(dir, sense);
        }
    }
}

// ---------------- launch ----------------
extern "C" void kernel_launch(void* const* d_in, const int* in_sizes, int n_in,
                              void* d_out, int out_size)
{
    (void)in_sizes; (void)n_in; (void)out_size;

    const float* x  = (const float*)d_in[0];
    const float* h0 = (const float*)d_in[1];
    const float* c0 = (const float*)d_in[2];
    const float* P[24];
    for (int i = 0; i < 24; i++) P[i] = (const float*)d_in[3 + i];
    // P[(l*2+d)*4 + {0:w_ih, 1:w_hh, 2:b_ih, 3:b_hh}]

    float* gxp = nullptr;
    __half *wih = nullptr, *act = nullptr;
    uint4* wrec = nullptr;
    cudaGetSymbolAddress((void**)&gxp,  g_gx);
    cudaGetSymbolAddress((void**)&wih,  g_wih);
    cudaGetSymbolAddress((void**)&act,  g_act);
    cudaGetSymbolAddress((void**)&wrec, g_wrec);
    cudaFuncSetAttribute(rec_kernel, cudaFuncAttributeMaxDynamicSharedMemorySize, REC_SMEM);
    cudaFuncSetAttribute(gemm_mma,   cudaFuncAttributeMaxDynamicSharedMemorySize, GEMM_SMEM);

    float* out = (float*)d_out;

    // launch 1: bake W_hh fp16 fragment streams
    W6 w6;
    for (int i = 0; i < 6; i++) w6.w[i] = P[i * 4 + 1];
    wrec_prep<<<dim3(64, 6), 256>>>(w6, wrec);

    // launch 2: convert all 6 w_ih to fp16
    W6 w6i;
    for (int i = 0; i < 6; i++) w6i.w[i] = P[i * 4];
    wih_split<<<dim3(8192, 6), 256>>>(w6i, wih);

    const size_t woff[6] = {0, 1310720, 2621440, 11010048, 19398656, 27787264};
    dim3 gg(GDIM / 128, MROWS / 128, 2), gb(256);

    // layer 0 (K=320, fp32 x converted in staging)
    gemm_mma<<<gg, gb, GEMM_SMEM>>>(320, x, nullptr,
                                    wih + woff[0], wih + woff[1],
                                    P[2], P[3], P[6], P[7], gxp);
    rec_kernel<<<128, 512, REC_SMEM>>>(wrec, h0, c0, 0, gxp, nullptr, act);

    // layer 1 (K=2048, pipelined)
    gemm_mma<<<gg, gb, GEMM_SMEM>>>(2048, nullptr, act,
                                    wih + woff[2], wih + woff[3],
                                    P[10], P[11], P[14], P[15], gxp);
    rec_kernel<<<128, 512, REC_SMEM>>>(wrec, h0, c0, 1, gxp, nullptr, act);

    // layer 2 (K=2048, pipelined) -> fp32 output
    gemm_mma<<<gg, gb, GEMM_SMEM>>>(2048, nullptr, act,
                                    wih + woff[4], wih + woff[5],
                                    P[18], P[19], P[22], P[23], gxp);
    rec_kernel<<<128, 512, REC_SMEM>>>(wrec, h0, c0, 2, gxp, out, nullptr);
}